// round 2
// baseline (speedup 1.0000x reference)
#include <cuda_runtime.h>
#include <cstdint>

// Problem constants (LangevinSDEContiformer: B=1024, S=512, H=64, D_IN=3)
#define BB   1024
#define SS   512
#define HH   64
#define DIN  3
#define SM1  511    // S-1 steps
#define H2   128    // 2*H

// ---------------------------------------------------------------------------
// Precomputed per-step diffusion scale: sigsc[s][h] = clip(softplus(...)+|mn|,|mn|,|mx|)*sqrt(hstep)
// ---------------------------------------------------------------------------
__device__ float d_sigsc[SM1 * HH];
__device__ float d_hstep[SM1];
__device__ float d_times[SM1];

__global__ void sigma_kernel(const float* __restrict__ ts,
                             const float* __restrict__ Wd1, const float* __restrict__ bd1,
                             const float* __restrict__ Wd2, const float* __restrict__ bd2,
                             const float* __restrict__ minp, const float* __restrict__ maxp)
{
    __shared__ float hh[32];
    int s = blockIdx.x;
    int tid = threadIdx.x;
    float t = ts[(size_t)s * DIN];           // time_series[0][s][0]
    if (tid < 32) hh[tid] = fmaxf(t * Wd1[tid] + bd1[tid], 0.0f);
    __syncthreads();
    float acc = bd2[tid];
    #pragma unroll
    for (int i = 0; i < 32; i++) acc += hh[i] * Wd2[i * HH + tid];
    // softplus(x) = max(x,0) + log1p(exp(-|x|))
    float sp = fmaxf(acc, 0.0f) + log1pf(expf(-fabsf(acc)));
    float mind = fabsf(minp[0]);
    float maxd = fabsf(maxp[0]);
    float sig = fminf(fmaxf(sp + mind, mind), maxd);
    float hs = ts[(size_t)(s + 1) * DIN] - t;
    d_sigsc[s * HH + tid] = sig * sqrtf(hs);
    if (tid == 0) { d_hstep[s] = hs; d_times[s] = t; }
}

// ---------------------------------------------------------------------------
// Main persistent scan kernel
//   grid = 128 CTAs x 128 threads. CTA owns 8 batch rows (2 groups of 4 rows).
//   Within a group: 2 warps, k-split over the reduction dimension.
//   Weights in shared with odd row strides (129 / 65) -> conflict-free for
//   both row-major (forward) and column (transposed, backward) access.
// ---------------------------------------------------------------------------
// shared layout (floats)
#define W1_STRIDE 129
#define W2_STRIDE 65
#define OFF_W1   0                       // 65 x 129  = 8385
#define OFF_W2   (OFF_W1 + 65*129)       // 128 x 65  = 8320  -> 16705
#define OFF_W3   (OFF_W2 + 128*65)       // 64               -> 16769
#define OFF_B1   (OFF_W3 + 64)           // 128              -> 16897
#define OFF_B2   (OFF_B1 + 128)          // 64               -> 16961
#define OFF_Y    (OFF_B2 + 64 + 3)       // 16964 (16B aligned), 8*64 = 512
#define OFF_H1   (OFF_Y + 8*64)          // 17476, 8*128 = 1024
#define OFF_G2   (OFF_H1 + 8*128)        // 18500, 8*64 = 512
#define OFF_G1   (OFF_G2 + 8*64)         // 19012, 8*128 = 1024
#define OFF_PART (OFF_G1 + 8*128)        // 20036, 16*128 = 2048
#define SMEM_FLOATS (OFF_PART + 16*128)  // 22084
#define SMEM_BYTES  (SMEM_FLOATS * 4)    // 88336

__device__ __forceinline__ float tanh_fast(float x) {
    float y;
    asm("tanh.approx.f32 %0, %1;" : "=f"(y) : "f"(x));
    return y;
}

__global__ void __launch_bounds__(128, 1)
sde_scan_kernel(const float* __restrict__ ts, const float* __restrict__ noise,
                const float* __restrict__ Wp1, const float* __restrict__ bp1,
                const float* __restrict__ Wp2, const float* __restrict__ bp2,
                const float* __restrict__ Wp3, float* __restrict__ out)
{
    extern __shared__ float sm[];
    float* W1  = sm + OFF_W1;   // [65][129]  Wp1[k][j]
    float* W2  = sm + OFF_W2;   // [128][65]  Wp2[k][j]
    float* W3  = sm + OFF_W3;   // [64]
    float* B1s = sm + OFF_B1;   // [128]
    float* B2s = sm + OFF_B2;   // [64]
    float* Y   = sm + OFF_Y;    // [8][64]
    float* H1s = sm + OFF_H1;   // [8][128]
    float* G2s = sm + OFF_G2;   // [8][64]
    float* G1s = sm + OFF_G1;   // [8][128]
    float* PART= sm + OFF_PART; // [16][128]   (group,parity,row) x 128

    const int tid  = threadIdx.x;
    const int lane = tid & 31;
    const int wid  = tid >> 5;
    const int g    = wid >> 1;      // row group 0/1
    const int p    = wid & 1;       // k-split parity
    const int rbase = g * 4;
    const int rowTop = blockIdx.x * 8;

    // ---- load weights into shared
    for (int i = tid; i < 65 * 128; i += 128) {
        int k = i >> 7, j = i & 127;
        W1[k * W1_STRIDE + j] = Wp1[i];
    }
    for (int i = tid; i < 128 * 64; i += 128) {
        int k = i >> 6, j = i & 63;
        W2[k * W2_STRIDE + j] = Wp2[i];
    }
    if (tid < 64) { W3[tid] = Wp3[tid]; B2s[tid] = bp2[tid]; }
    B1s[tid] = bp1[tid];

    // ---- init y0 and write out[:,0,:]
    #pragma unroll
    for (int q = 0; q < 4; q++) {
        int e = q * 128 + tid;
        int k = e & 63, r8 = e >> 6;
        int b = rowTop + r8;
        float v = (k < DIN) ? ts[(size_t)b * SS * DIN + k] : 0.0f;
        Y[r8 * 64 + k] = v;
        out[((size_t)b * SS) * HH + k] = v;
    }
    __syncthreads();

    for (int s = 0; s < SM1; s++) {
        const float tcur  = d_times[s];
        const float hstep = d_hstep[s];

        // prefetch noise * sigsc for this step (consumed ~4000 cycles later)
        float zs[4];
        #pragma unroll
        for (int q = 0; q < 4; q++) {
            int e = q * 128 + tid;
            int k = e & 63, r8 = e >> 6;
            int b = rowTop + r8;
            zs[q] = d_sigsc[s * HH + k] *
                    noise[((size_t)s * BB + b) * HH + k];
        }

        // ================= phase 1: h1 = tanh([y,t] @ W1 + b1) ==============
        {
            float acc[4][4];
            if (p == 0) {
                #pragma unroll
                for (int m = 0; m < 4; m++) {
                    int j = lane + 32 * m;
                    float init = fmaf(tcur, W1[64 * W1_STRIDE + j], B1s[j]);
                    #pragma unroll
                    for (int r = 0; r < 4; r++) acc[r][m] = init;
                }
            } else {
                #pragma unroll
                for (int r = 0; r < 4; r++)
                    #pragma unroll
                    for (int m = 0; m < 4; m++) acc[r][m] = 0.0f;
            }
            const int kb = p * 32;
            #pragma unroll 4
            for (int kk = 0; kk < 8; kk++) {
                float4 yv[4];
                #pragma unroll
                for (int r = 0; r < 4; r++)
                    yv[r] = *(const float4*)&Y[(rbase + r) * 64 + kb + kk * 4];
                #pragma unroll
                for (int q = 0; q < 4; q++) {
                    float w[4];
                    #pragma unroll
                    for (int m = 0; m < 4; m++)
                        w[m] = W1[(kb + kk * 4 + q) * W1_STRIDE + lane + 32 * m];
                    #pragma unroll
                    for (int r = 0; r < 4; r++) {
                        float yq = (&yv[r].x)[q];
                        #pragma unroll
                        for (int m = 0; m < 4; m++)
                            acc[r][m] = fmaf(yq, w[m], acc[r][m]);
                    }
                }
            }
            #pragma unroll
            for (int r = 0; r < 4; r++)
                #pragma unroll
                for (int m = 0; m < 4; m++)
                    PART[((g * 2 + p) * 4 + r) * 128 + lane + 32 * m] = acc[r][m];
        }
        __syncthreads();
        #pragma unroll
        for (int q = 0; q < 8; q++) {
            int e = q * 128 + tid;
            int j = e & 127, r8 = e >> 7;
            int gg = r8 >> 2, r = r8 & 3;
            float sum = PART[((gg * 2) * 4 + r) * 128 + j]
                      + PART[((gg * 2 + 1) * 4 + r) * 128 + j];
            H1s[r8 * 128 + j] = tanh_fast(sum);
        }
        __syncthreads();

        // ====== phase 2: h2 = tanh(h1 @ W2 + b2); g2 = W3*(1-h2^2) ==========
        {
            float acc[4][2];
            #pragma unroll
            for (int m = 0; m < 2; m++) {
                float init = (p == 0) ? B2s[lane + 32 * m] : 0.0f;
                #pragma unroll
                for (int r = 0; r < 4; r++) acc[r][m] = init;
            }
            const int kb = p * 64;
            #pragma unroll 4
            for (int kk = 0; kk < 16; kk++) {
                float4 hv[4];
                #pragma unroll
                for (int r = 0; r < 4; r++)
                    hv[r] = *(const float4*)&H1s[(rbase + r) * 128 + kb + kk * 4];
                #pragma unroll
                for (int q = 0; q < 4; q++) {
                    float w[2];
                    #pragma unroll
                    for (int m = 0; m < 2; m++)
                        w[m] = W2[(kb + kk * 4 + q) * W2_STRIDE + lane + 32 * m];
                    #pragma unroll
                    for (int r = 0; r < 4; r++) {
                        float hq = (&hv[r].x)[q];
                        #pragma unroll
                        for (int m = 0; m < 2; m++)
                            acc[r][m] = fmaf(hq, w[m], acc[r][m]);
                    }
                }
            }
            #pragma unroll
            for (int r = 0; r < 4; r++)
                #pragma unroll
                for (int m = 0; m < 2; m++)
                    PART[((g * 2 + p) * 4 + r) * 128 + lane + 32 * m] = acc[r][m];
        }
        __syncthreads();
        #pragma unroll
        for (int q = 0; q < 4; q++) {
            int e = q * 128 + tid;
            int j = e & 63, r8 = e >> 6;
            int gg = r8 >> 2, r = r8 & 3;
            float sum = PART[((gg * 2) * 4 + r) * 128 + j]
                      + PART[((gg * 2 + 1) * 4 + r) * 128 + j];
            float h2 = tanh_fast(sum);
            G2s[r8 * 64 + j] = W3[j] * (1.0f - h2 * h2);
        }
        __syncthreads();

        // ====== phase 3: g1 = (g2 @ W2^T) * (1 - h1^2) =======================
        {
            float acc[4][4];
            #pragma unroll
            for (int r = 0; r < 4; r++)
                #pragma unroll
                for (int m = 0; m < 4; m++) acc[r][m] = 0.0f;
            const int jb = p * 32;
            #pragma unroll 4
            for (int jj = 0; jj < 8; jj++) {
                float4 gv[4];
                #pragma unroll
                for (int r = 0; r < 4; r++)
                    gv[r] = *(const float4*)&G2s[(rbase + r) * 64 + jb + jj * 4];
                #pragma unroll
                for (int q = 0; q < 4; q++) {
                    float w[4];
                    #pragma unroll
                    for (int m = 0; m < 4; m++)   // column access, stride 65 -> conflict-free
                        w[m] = W2[(lane + 32 * m) * W2_STRIDE + jb + jj * 4 + q];
                    #pragma unroll
                    for (int r = 0; r < 4; r++) {
                        float gq = (&gv[r].x)[q];
                        #pragma unroll
                        for (int m = 0; m < 4; m++)
                            acc[r][m] = fmaf(gq, w[m], acc[r][m]);
                    }
                }
            }
            #pragma unroll
            for (int r = 0; r < 4; r++)
                #pragma unroll
                for (int m = 0; m < 4; m++)
                    PART[((g * 2 + p) * 4 + r) * 128 + lane + 32 * m] = acc[r][m];
        }
        __syncthreads();
        #pragma unroll
        for (int q = 0; q < 8; q++) {
            int e = q * 128 + tid;
            int i = e & 127, r8 = e >> 7;
            int gg = r8 >> 2, r = r8 & 3;
            float sum = PART[((gg * 2) * 4 + r) * 128 + i]
                      + PART[((gg * 2 + 1) * 4 + r) * 128 + i];
            float h1v = H1s[r8 * 128 + i];
            G1s[r8 * 128 + i] = sum * (1.0f - h1v * h1v);
        }
        __syncthreads();

        // ====== phase 4: dy = g1 @ W1[:64,:]^T ; y += -dy*h + sig*z*sqrt(h) ==
        {
            float acc[4][2];
            #pragma unroll
            for (int r = 0; r < 4; r++)
                #pragma unroll
                for (int m = 0; m < 2; m++) acc[r][m] = 0.0f;
            const int ib = p * 64;
            #pragma unroll 4
            for (int ii = 0; ii < 16; ii++) {
                float4 g1v[4];
                #pragma unroll
                for (int r = 0; r < 4; r++)
                    g1v[r] = *(const float4*)&G1s[(rbase + r) * 128 + ib + ii * 4];
                #pragma unroll
                for (int q = 0; q < 4; q++) {
                    float w[2];
                    #pragma unroll
                    for (int m = 0; m < 2; m++)   // column access, stride 129 -> conflict-free
                        w[m] = W1[(lane + 32 * m) * W1_STRIDE + ib + ii * 4 + q];
                    #pragma unroll
                    for (int r = 0; r < 4; r++) {
                        float gq = (&g1v[r].x)[q];
                        #pragma unroll
                        for (int m = 0; m < 2; m++)
                            acc[r][m] = fmaf(gq, w[m], acc[r][m]);
                    }
                }
            }
            #pragma unroll
            for (int r = 0; r < 4; r++)
                #pragma unroll
                for (int m = 0; m < 2; m++)
                    PART[((g * 2 + p) * 4 + r) * 128 + lane + 32 * m] = acc[r][m];
        }
        __syncthreads();
        #pragma unroll
        for (int q = 0; q < 4; q++) {
            int e = q * 128 + tid;
            int k = e & 63, r8 = e >> 6;
            int gg = r8 >> 2, r = r8 & 3;
            float dy = PART[((gg * 2) * 4 + r) * 128 + k]
                     + PART[((gg * 2 + 1) * 4 + r) * 128 + k];
            float ynew = fmaf(-dy, hstep, Y[r8 * 64 + k]) + zs[q];
            Y[r8 * 64 + k] = ynew;
            int b = rowTop + r8;
            out[((size_t)b * SS + (s + 1)) * HH + k] = ynew;
        }
        __syncthreads();
    }
}

// ---------------------------------------------------------------------------
extern "C" void kernel_launch(void* const* d_in, const int* in_sizes, int n_in,
                              void* d_out, int out_size)
{
    (void)in_sizes; (void)n_in; (void)out_size;
    const float* ts    = (const float*)d_in[0];   // time_series (B,S,3)
    const float* noise = (const float*)d_in[1];   // (S-1,B,H)
    const float* Wp1   = (const float*)d_in[2];   // (65,128)
    const float* bp1   = (const float*)d_in[3];   // (128,)
    const float* Wp2   = (const float*)d_in[4];   // (128,64)
    const float* bp2   = (const float*)d_in[5];   // (64,)
    const float* Wp3   = (const float*)d_in[6];   // (64,1)
    // d_in[7] = bp3 (unused: constant shift, zero gradient)
    const float* Wd1   = (const float*)d_in[8];   // (1,32)
    const float* bd1   = (const float*)d_in[9];   // (32,)
    const float* Wd2   = (const float*)d_in[10];  // (32,64)
    const float* bd2   = (const float*)d_in[11];  // (64,)
    const float* mn    = (const float*)d_in[12];  // scalar
    const float* mx    = (const float*)d_in[13];  // scalar
    float* out = (float*)d_out;

    cudaFuncSetAttribute(sde_scan_kernel,
                         cudaFuncAttributeMaxDynamicSharedMemorySize, SMEM_BYTES);

    sigma_kernel<<<SM1, HH>>>(ts, Wd1, bd1, Wd2, bd2, mn, mx);
    sde_scan_kernel<<<BB / 8, 128, SMEM_BYTES>>>(ts, noise, Wp1, bp1, Wp2, bp2, Wp3, out);
}

// round 3
// speedup vs baseline: 1.0995x; 1.0995x over previous
#include <cuda_runtime.h>
#include <cstdint>

// Problem constants (LangevinSDEContiformer: B=1024, S=512, H=64, D_IN=3)
#define BB   1024
#define SS   512
#define HH   64
#define DIN  3
#define SM1  511    // S-1 steps
#define H2   128    // 2*H

__device__ float d_sigsc[SM1 * HH];
__device__ float d_hstep[SM1];
__device__ float d_times[SM1];

__global__ void sigma_kernel(const float* __restrict__ ts,
                             const float* __restrict__ Wd1, const float* __restrict__ bd1,
                             const float* __restrict__ Wd2, const float* __restrict__ bd2,
                             const float* __restrict__ minp, const float* __restrict__ maxp)
{
    __shared__ float hh[32];
    int s = blockIdx.x;
    int tid = threadIdx.x;
    float t = ts[(size_t)s * DIN];           // time_series[0][s][0]
    if (tid < 32) hh[tid] = fmaxf(t * Wd1[tid] + bd1[tid], 0.0f);
    __syncthreads();
    float acc = bd2[tid];
    #pragma unroll
    for (int i = 0; i < 32; i++) acc += hh[i] * Wd2[i * HH + tid];
    float sp = fmaxf(acc, 0.0f) + log1pf(expf(-fabsf(acc)));
    float mind = fabsf(minp[0]);
    float maxd = fabsf(maxp[0]);
    float sig = fminf(fmaxf(sp + mind, mind), maxd);
    float hs = ts[(size_t)(s + 1) * DIN] - t;
    d_sigsc[s * HH + tid] = sig * sqrtf(hs);
    if (tid == 0) { d_hstep[s] = hs; d_times[s] = t; }
}

// ---------------------------------------------------------------------------
// Main persistent scan kernel
//   grid = 128 CTAs x 256 threads. CTA owns 8 batch rows (2 groups of 4 rows).
//   Within a group: 4 warps, k-split-4 over the reduction dimension.
//   (2 warps per SMSP -> latency hiding; r=4 row-blocking preserved -> each
//    weight LDS feeds 4 FMAs; odd strides 129/65 -> conflict-free row+col.)
// ---------------------------------------------------------------------------
#define W1_STRIDE 129
#define W2_STRIDE 65
#define OFF_W1   0                       // 65 x 129  = 8385
#define OFF_W2   (OFF_W1 + 65*129)       // 128 x 65  = 8320  -> 16705
#define OFF_W3   (OFF_W2 + 128*65)       // 64
#define OFF_B1   (OFF_W3 + 64)           // 128
#define OFF_B2   (OFF_B1 + 128)          // 64
#define OFF_Y    (OFF_B2 + 64 + 3)       // 16964 (16B aligned), 8*64
#define OFF_H1   (OFF_Y + 8*64)          // 8*128
#define OFF_G2   (OFF_H1 + 8*128)        // 8*64
#define OFF_G1   (OFF_G2 + 8*64)         // 8*128
#define OFF_PART (OFF_G1 + 8*128)        // 32*128 = 4096
#define SMEM_FLOATS (OFF_PART + 32*128)  // 24132
#define SMEM_BYTES  (SMEM_FLOATS * 4)    // 96528

__device__ __forceinline__ float tanh_fast(float x) {
    float y;
    asm("tanh.approx.f32 %0, %1;" : "=f"(y) : "f"(x));
    return y;
}

__global__ void __launch_bounds__(256, 1)
sde_scan_kernel(const float* __restrict__ ts, const float* __restrict__ noise,
                const float* __restrict__ Wp1, const float* __restrict__ bp1,
                const float* __restrict__ Wp2, const float* __restrict__ bp2,
                const float* __restrict__ Wp3, float* __restrict__ out)
{
    extern __shared__ float sm[];
    float* W1  = sm + OFF_W1;   // [65][129]  Wp1[k][j]
    float* W2  = sm + OFF_W2;   // [128][65]  Wp2[k][j]
    float* W3  = sm + OFF_W3;   // [64]
    float* B1s = sm + OFF_B1;   // [128]
    float* B2s = sm + OFF_B2;   // [64]
    float* Y   = sm + OFF_Y;    // [8][64]
    float* H1s = sm + OFF_H1;   // [8][128]
    float* G2s = sm + OFF_G2;   // [8][64]
    float* G1s = sm + OFF_G1;   // [8][128]
    float* PART= sm + OFF_PART; // [32][128]   (group,parity,row) x 128

    const int tid  = threadIdx.x;
    const int lane = tid & 31;
    const int wid  = tid >> 5;
    const int g    = wid >> 2;      // row group 0/1
    const int p    = wid & 3;       // k-split parity 0..3
    const int rbase = g * 4;
    const int rowTop = blockIdx.x * 8;

    // ---- load weights into shared
    for (int i = tid; i < 65 * 128; i += 256) {
        int k = i >> 7, j = i & 127;
        W1[k * W1_STRIDE + j] = Wp1[i];
    }
    for (int i = tid; i < 128 * 64; i += 256) {
        int k = i >> 6, j = i & 63;
        W2[k * W2_STRIDE + j] = Wp2[i];
    }
    if (tid < 64) { W3[tid] = Wp3[tid]; B2s[tid] = bp2[tid]; }
    if (tid < 128) B1s[tid] = bp1[tid];

    // ---- init y0 and write out[:,0,:]
    #pragma unroll
    for (int q = 0; q < 2; q++) {
        int e = q * 256 + tid;
        int k = e & 63, r8 = e >> 6;
        int b = rowTop + r8;
        float v = (k < DIN) ? ts[(size_t)b * SS * DIN + k] : 0.0f;
        Y[r8 * 64 + k] = v;
        out[((size_t)b * SS) * HH + k] = v;
    }
    __syncthreads();

    for (int s = 0; s < SM1; s++) {
        const float tcur  = d_times[s];
        const float hstep = d_hstep[s];

        // prefetch noise * sigsc (consumed at end of step)
        float zs[2];
        #pragma unroll
        for (int q = 0; q < 2; q++) {
            int e = q * 256 + tid;
            int k = e & 63, r8 = e >> 6;
            int b = rowTop + r8;
            zs[q] = d_sigsc[s * HH + k] *
                    noise[((size_t)s * BB + b) * HH + k];
        }

        // ================= phase 1: h1 = tanh([y,t] @ W1 + b1) ==============
        {
            float acc[4][4];
            if (p == 0) {
                #pragma unroll
                for (int m = 0; m < 4; m++) {
                    int j = lane + 32 * m;
                    float init = fmaf(tcur, W1[64 * W1_STRIDE + j], B1s[j]);
                    #pragma unroll
                    for (int r = 0; r < 4; r++) acc[r][m] = init;
                }
            } else {
                #pragma unroll
                for (int r = 0; r < 4; r++)
                    #pragma unroll
                    for (int m = 0; m < 4; m++) acc[r][m] = 0.0f;
            }
            const int kb = p * 16;
            #pragma unroll
            for (int kk = 0; kk < 4; kk++) {
                float4 yv[4];
                #pragma unroll
                for (int r = 0; r < 4; r++)
                    yv[r] = *(const float4*)&Y[(rbase + r) * 64 + kb + kk * 4];
                #pragma unroll
                for (int q = 0; q < 4; q++) {
                    float w[4];
                    #pragma unroll
                    for (int m = 0; m < 4; m++)
                        w[m] = W1[(kb + kk * 4 + q) * W1_STRIDE + lane + 32 * m];
                    #pragma unroll
                    for (int r = 0; r < 4; r++) {
                        float yq = (&yv[r].x)[q];
                        #pragma unroll
                        for (int m = 0; m < 4; m++)
                            acc[r][m] = fmaf(yq, w[m], acc[r][m]);
                    }
                }
            }
            #pragma unroll
            for (int r = 0; r < 4; r++)
                #pragma unroll
                for (int m = 0; m < 4; m++)
                    PART[((g * 4 + p) * 4 + r) * 128 + lane + 32 * m] = acc[r][m];
        }
        __syncthreads();
        #pragma unroll
        for (int q = 0; q < 4; q++) {
            int e = q * 256 + tid;
            int j = e & 127, r8 = e >> 7;
            int gg = r8 >> 2, r = r8 & 3;
            float sum = (PART[((gg * 4 + 0) * 4 + r) * 128 + j]
                       + PART[((gg * 4 + 1) * 4 + r) * 128 + j])
                      + (PART[((gg * 4 + 2) * 4 + r) * 128 + j]
                       + PART[((gg * 4 + 3) * 4 + r) * 128 + j]);
            H1s[r8 * 128 + j] = tanh_fast(sum);
        }
        __syncthreads();

        // ====== phase 2: h2 = tanh(h1 @ W2 + b2); g2 = W3*(1-h2^2) ==========
        {
            float acc[4][2];
            #pragma unroll
            for (int m = 0; m < 2; m++) {
                float init = (p == 0) ? B2s[lane + 32 * m] : 0.0f;
                #pragma unroll
                for (int r = 0; r < 4; r++) acc[r][m] = init;
            }
            const int kb = p * 32;
            #pragma unroll
            for (int kk = 0; kk < 8; kk++) {
                float4 hv[4];
                #pragma unroll
                for (int r = 0; r < 4; r++)
                    hv[r] = *(const float4*)&H1s[(rbase + r) * 128 + kb + kk * 4];
                #pragma unroll
                for (int q = 0; q < 4; q++) {
                    float w[2];
                    #pragma unroll
                    for (int m = 0; m < 2; m++)
                        w[m] = W2[(kb + kk * 4 + q) * W2_STRIDE + lane + 32 * m];
                    #pragma unroll
                    for (int r = 0; r < 4; r++) {
                        float hq = (&hv[r].x)[q];
                        #pragma unroll
                        for (int m = 0; m < 2; m++)
                            acc[r][m] = fmaf(hq, w[m], acc[r][m]);
                    }
                }
            }
            #pragma unroll
            for (int r = 0; r < 4; r++)
                #pragma unroll
                for (int m = 0; m < 2; m++)
                    PART[((g * 4 + p) * 4 + r) * 128 + lane + 32 * m] = acc[r][m];
        }
        __syncthreads();
        #pragma unroll
        for (int q = 0; q < 2; q++) {
            int e = q * 256 + tid;
            int j = e & 63, r8 = e >> 6;
            int gg = r8 >> 2, r = r8 & 3;
            float sum = (PART[((gg * 4 + 0) * 4 + r) * 128 + j]
                       + PART[((gg * 4 + 1) * 4 + r) * 128 + j])
                      + (PART[((gg * 4 + 2) * 4 + r) * 128 + j]
                       + PART[((gg * 4 + 3) * 4 + r) * 128 + j]);
            float h2 = tanh_fast(sum);
            G2s[r8 * 64 + j] = W3[j] * (1.0f - h2 * h2);
        }
        __syncthreads();

        // ====== phase 3: g1 = (g2 @ W2^T) * (1 - h1^2) =======================
        {
            float acc[4][4];
            #pragma unroll
            for (int r = 0; r < 4; r++)
                #pragma unroll
                for (int m = 0; m < 4; m++) acc[r][m] = 0.0f;
            const int jb = p * 16;
            #pragma unroll
            for (int jj = 0; jj < 4; jj++) {
                float4 gv[4];
                #pragma unroll
                for (int r = 0; r < 4; r++)
                    gv[r] = *(const float4*)&G2s[(rbase + r) * 64 + jb + jj * 4];
                #pragma unroll
                for (int q = 0; q < 4; q++) {
                    float w[4];
                    #pragma unroll
                    for (int m = 0; m < 4; m++)   // column access, stride 65 -> conflict-free
                        w[m] = W2[(lane + 32 * m) * W2_STRIDE + jb + jj * 4 + q];
                    #pragma unroll
                    for (int r = 0; r < 4; r++) {
                        float gq = (&gv[r].x)[q];
                        #pragma unroll
                        for (int m = 0; m < 4; m++)
                            acc[r][m] = fmaf(gq, w[m], acc[r][m]);
                    }
                }
            }
            #pragma unroll
            for (int r = 0; r < 4; r++)
                #pragma unroll
                for (int m = 0; m < 4; m++)
                    PART[((g * 4 + p) * 4 + r) * 128 + lane + 32 * m] = acc[r][m];
        }
        __syncthreads();
        #pragma unroll
        for (int q = 0; q < 4; q++) {
            int e = q * 256 + tid;
            int i = e & 127, r8 = e >> 7;
            int gg = r8 >> 2, r = r8 & 3;
            float sum = (PART[((gg * 4 + 0) * 4 + r) * 128 + i]
                       + PART[((gg * 4 + 1) * 4 + r) * 128 + i])
                      + (PART[((gg * 4 + 2) * 4 + r) * 128 + i]
                       + PART[((gg * 4 + 3) * 4 + r) * 128 + i]);
            float h1v = H1s[r8 * 128 + i];
            G1s[r8 * 128 + i] = sum * (1.0f - h1v * h1v);
        }
        __syncthreads();

        // ====== phase 4: dy = g1 @ W1[:64,:]^T ; y += -dy*h + sig*z*sqrt(h) ==
        {
            float acc[4][2];
            #pragma unroll
            for (int r = 0; r < 4; r++)
                #pragma unroll
                for (int m = 0; m < 2; m++) acc[r][m] = 0.0f;
            const int ib = p * 32;
            #pragma unroll
            for (int ii = 0; ii < 8; ii++) {
                float4 g1v[4];
                #pragma unroll
                for (int r = 0; r < 4; r++)
                    g1v[r] = *(const float4*)&G1s[(rbase + r) * 128 + ib + ii * 4];
                #pragma unroll
                for (int q = 0; q < 4; q++) {
                    float w[2];
                    #pragma unroll
                    for (int m = 0; m < 2; m++)   // column access, stride 129 -> conflict-free
                        w[m] = W1[(lane + 32 * m) * W1_STRIDE + ib + ii * 4 + q];
                    #pragma unroll
                    for (int r = 0; r < 4; r++) {
                        float gq = (&g1v[r].x)[q];
                        #pragma unroll
                        for (int m = 0; m < 2; m++)
                            acc[r][m] = fmaf(gq, w[m], acc[r][m]);
                    }
                }
            }
            #pragma unroll
            for (int r = 0; r < 4; r++)
                #pragma unroll
                for (int m = 0; m < 2; m++)
                    PART[((g * 4 + p) * 4 + r) * 128 + lane + 32 * m] = acc[r][m];
        }
        __syncthreads();
        #pragma unroll
        for (int q = 0; q < 2; q++) {
            int e = q * 256 + tid;
            int k = e & 63, r8 = e >> 6;
            int gg = r8 >> 2, r = r8 & 3;
            float dy = (PART[((gg * 4 + 0) * 4 + r) * 128 + k]
                      + PART[((gg * 4 + 1) * 4 + r) * 128 + k])
                     + (PART[((gg * 4 + 2) * 4 + r) * 128 + k]
                      + PART[((gg * 4 + 3) * 4 + r) * 128 + k]);
            float ynew = fmaf(-dy, hstep, Y[r8 * 64 + k]) + zs[q];
            Y[r8 * 64 + k] = ynew;
            int b = rowTop + r8;
            out[((size_t)b * SS + (s + 1)) * HH + k] = ynew;
        }
        __syncthreads();
    }
}

// ---------------------------------------------------------------------------
extern "C" void kernel_launch(void* const* d_in, const int* in_sizes, int n_in,
                              void* d_out, int out_size)
{
    (void)in_sizes; (void)n_in; (void)out_size;
    const float* ts    = (const float*)d_in[0];   // time_series (B,S,3)
    const float* noise = (const float*)d_in[1];   // (S-1,B,H)
    const float* Wp1   = (const float*)d_in[2];   // (65,128)
    const float* bp1   = (const float*)d_in[3];   // (128,)
    const float* Wp2   = (const float*)d_in[4];   // (128,64)
    const float* bp2   = (const float*)d_in[5];   // (64,)
    const float* Wp3   = (const float*)d_in[6];   // (64,1)
    // d_in[7] = bp3 (unused: constant shift, zero gradient)
    const float* Wd1   = (const float*)d_in[8];   // (1,32)
    const float* bd1   = (const float*)d_in[9];   // (32,)
    const float* Wd2   = (const float*)d_in[10];  // (32,64)
    const float* bd2   = (const float*)d_in[11];  // (64,)
    const float* mn    = (const float*)d_in[12];  // scalar
    const float* mx    = (const float*)d_in[13];  // scalar
    float* out = (float*)d_out;

    cudaFuncSetAttribute(sde_scan_kernel,
                         cudaFuncAttributeMaxDynamicSharedMemorySize, SMEM_BYTES);

    sigma_kernel<<<SM1, HH>>>(ts, Wd1, bd1, Wd2, bd2, mn, mx);
    sde_scan_kernel<<<BB / 8, 256, SMEM_BYTES>>>(ts, noise, Wp1, bp1, Wp2, bp2, Wp3, out);
}